// round 16
// baseline (speedup 1.0000x reference)
#include <cuda_runtime.h>
#include <cuda_fp16.h>
#include <cstdint>

// Problem constants
#define BATCH 2
#define SEQ   2048
#define DMODEL 1024
#define NHEADS 16
#define DK 64
#define M_TOK (BATCH*SEQ)          // 4096

// Q pre-scale: (1/sqrt(64)) * log2(e)  -> scores arrive in log2 units
#define QSCALE 0.1803368801111855f

// Scratch (no allocations allowed -> __device__ globals).  All fp16.
__device__ __half g_q[BATCH*NHEADS*SEQ*DK];     // pre-scaled by QSCALE
__device__ __half g_k[BATCH*NHEADS*SEQ*DK];
__device__ __half g_v[BATCH*NHEADS*SEQ*DK];
__device__ __half g_attn[M_TOK*DMODEL];
__device__ __half g_x[M_TOK*DMODEL];
__device__ __half g_wqkv[3*DMODEL*DMODEL];
__device__ __half g_wo[DMODEL*DMODEL];

// ---------------------------------------------------------------------------
// helpers
// ---------------------------------------------------------------------------
__device__ __forceinline__ uint32_t smem_u32(const void* p) {
    uint32_t a;
    asm("{ .reg .u64 t; cvta.to.shared.u64 t, %1; cvt.u32.u64 %0, t; }"
        : "=r"(a) : "l"(p));
    return a;
}
__device__ __forceinline__ void cp_async16(uint32_t saddr, const void* gaddr) {
    asm volatile("cp.async.cg.shared.global [%0], [%1], 16;"
                 :: "r"(saddr), "l"(gaddr));
}
__device__ __forceinline__ void cp_commit() {
    asm volatile("cp.async.commit_group;");
}
__device__ __forceinline__ void ldsm_x4(uint32_t& r0, uint32_t& r1,
                                        uint32_t& r2, uint32_t& r3, uint32_t addr) {
    asm volatile("ldmatrix.sync.aligned.m8n8.x4.shared.b16 {%0,%1,%2,%3}, [%4];"
                 : "=r"(r0), "=r"(r1), "=r"(r2), "=r"(r3) : "r"(addr));
}
__device__ __forceinline__ void ldsm_x4_t(uint32_t& r0, uint32_t& r1,
                                          uint32_t& r2, uint32_t& r3, uint32_t addr) {
    asm volatile("ldmatrix.sync.aligned.m8n8.x4.trans.shared.b16 {%0,%1,%2,%3}, [%4];"
                 : "=r"(r0), "=r"(r1), "=r"(r2), "=r"(r3) : "r"(addr));
}
__device__ __forceinline__ uint32_t h2pack(float lo, float hi) {
    __half2 h = __floats2half2_rn(lo, hi);   // .x = lo (bits 0-15)
    return *(uint32_t*)&h;
}
__device__ __forceinline__ float ex2(float x) {
    float y;
    asm("ex2.approx.f32 %0, %1;" : "=f"(y) : "f"(x));
    return y;
}
__device__ __forceinline__ void mma_f16_16x8x16(
    float& d0, float& d1, float& d2, float& d3,
    uint32_t a0, uint32_t a1, uint32_t a2, uint32_t a3,
    uint32_t b0, uint32_t b1)
{
    asm volatile(
        "mma.sync.aligned.m16n8k16.row.col.f32.f16.f16.f32 "
        "{%0,%1,%2,%3}, {%4,%5,%6,%7}, {%8,%9}, {%0,%1,%2,%3};"
        : "+f"(d0), "+f"(d1), "+f"(d2), "+f"(d3)
        : "r"(a0), "r"(a1), "r"(a2), "r"(a3), "r"(b0), "r"(b1));
}

#define SHFL_XOR(v, m) __shfl_xor_sync(0xffffffffu, v, m)

// ---------------------------------------------------------------------------
// Pre-pass (single launch): fp32 -> fp16 round for x, w_qkv, w_o.
// ---------------------------------------------------------------------------
#define N4_X    (M_TOK*DMODEL/4)            // 1048576
#define N4_WQKV (3*DMODEL*DMODEL/4)         // 786432
#define N4_WO   (DMODEL*DMODEL/4)           // 262144
#define N4_TOT  (N4_X + N4_WQKV + N4_WO)    // 2097152

__global__ __launch_bounds__(256)
void roundcopy_all(const float4* __restrict__ sx, const float4* __restrict__ swq,
                   const float4* __restrict__ swo)
{
    __half2 *dx  = (__half2*)g_x;
    __half2 *dwq = (__half2*)g_wqkv;
    __half2 *dwo = (__half2*)g_wo;
    for (int i = blockIdx.x*blockDim.x + threadIdx.x; i < N4_TOT;
         i += gridDim.x*blockDim.x) {
        const float4* s; __half2* d; int j;
        if (i < N4_X)                { s = sx;  d = dx;  j = i; }
        else if (i < N4_X + N4_WQKV) { s = swq; d = dwq; j = i - N4_X; }
        else                         { s = swo; d = dwo; j = i - N4_X - N4_WQKV; }
        float4 v = s[j];
        d[2*j]   = __floats2half2_rn(v.x, v.y);
        d[2*j+1] = __floats2half2_rn(v.z, v.w);
    }
}

// ===========================================================================
// fp16 tensor-core GEMM (unchanged from R15): C = A@B^T + bias.
// 128x128 tile, BK=64, 3-stage cp.async pipeline, ldmatrix fragments.
// mode 0: scatter fp16 into g_q (xQSCALE) / g_k / g_v; mode 1: fp32 C write.
// ===========================================================================
#define BM 128
#define BN 128
#define ROWB 144                         // bytes per smem row (72 halves)
#define OPB  (128*ROWB)                  // 18432 B per operand per stage
#define STAGEB (2*OPB)                   // 36864 B
#define NSTAGE 3
#define GEMM_SMEM_BYTES (NSTAGE*STAGEB)  // 110592 B

__global__ __launch_bounds__(256)
void mma_gemm(const __half* __restrict__ A, const __half* __restrict__ B,
              const float* __restrict__ bias, float* __restrict__ C,
              int M, int N, int K, int mode)
{
    extern __shared__ char smx[];
    const uint32_t sbase = smem_u32(smx);

    const int tid = threadIdx.x;
    const int wid = tid >> 5;
    const int lane = tid & 31;
    const int gid = lane >> 2;
    const int tig = lane & 3;
    const int warpM = wid >> 2;
    const int warpN = wid & 3;
    const int bm = blockIdx.y, bn = blockIdx.x;

    const __half* Abase = A + (size_t)(bm*BM)*K;
    const __half* Bbase = B + (size_t)(bn*BN)*K;

    const int a_row  = lane & 15;
    const int a_colB = (lane >> 4)*16;
    const int b_row  = (lane & 7) + ((lane >> 4) & 1)*8;
    const int b_colB = ((lane >> 3) & 1)*16;

    float acc[4][4][4];
#pragma unroll
    for (int i = 0; i < 4; i++)
#pragma unroll
        for (int j = 0; j < 4; j++)
#pragma unroll
            for (int r = 0; r < 4; r++) acc[i][j][r] = 0.f;

    const int NC = K / 64;

    auto copy_stage = [&](int c, int st) {
        const uint32_t abuf = sbase + (uint32_t)st*STAGEB;
        const uint32_t bbuf = abuf + OPB;
        const int k0 = c * 64;
#pragma unroll
        for (int i = 0; i < 4; i++) {
            const int idx = tid + i*256;
            const int row = idx >> 3;            // 0..127
            const int c8  = idx & 7;
            const uint32_t soff = (uint32_t)(row*ROWB + c8*16);
            cp_async16(abuf + soff, Abase + (size_t)row*K + k0 + c8*8);
            cp_async16(bbuf + soff, Bbase + (size_t)row*K + k0 + c8*8);
        }
        cp_commit();
    };

    copy_stage(0, 0);
    copy_stage(1, 1);

    int cs = 0;
    for (int c = 0; c < NC; c++) {
        if (c + 1 < NC) {
            asm volatile("cp.async.wait_group 1;");
        } else {
            asm volatile("cp.async.wait_group 0;");
        }
        __syncthreads();

        if (c + 2 < NC) {
            int ps = cs + 2; if (ps >= NSTAGE) ps -= NSTAGE;
            copy_stage(c + 2, ps);
        }

        const uint32_t stage_base = sbase + (uint32_t)cs*STAGEB;
        const uint32_t aAddr = stage_base
            + (uint32_t)((warpM*64 + a_row)*ROWB + a_colB);
        const uint32_t bAddr = stage_base + OPB
            + (uint32_t)((warpN*32 + b_row)*ROWB + b_colB);

#pragma unroll
        for (int ks = 0; ks < 4; ks++) {
            const uint32_t ko = ks*32;           // 16 halves
            uint32_t bf[2][4];
            ldsm_x4(bf[0][0], bf[0][1], bf[0][2], bf[0][3], bAddr + ko);
            ldsm_x4(bf[1][0], bf[1][1], bf[1][2], bf[1][3],
                    bAddr + 16*ROWB + ko);
#pragma unroll
            for (int mt = 0; mt < 4; mt++) {
                uint32_t a0, a1, a2, a3;
                ldsm_x4(a0, a1, a2, a3, aAddr + (uint32_t)mt*16*ROWB + ko);
#pragma unroll
                for (int ntp = 0; ntp < 2; ntp++) {
#pragma unroll
                    for (int sub = 0; sub < 2; sub++) {
                        const int nt = ntp*2 + sub;
                        mma_f16_16x8x16(acc[mt][nt][0], acc[mt][nt][1],
                                        acc[mt][nt][2], acc[mt][nt][3],
                                        a0, a1, a2, a3,
                                        bf[ntp][sub*2], bf[ntp][sub*2+1]);
                    }
                }
            }
        }
        cs = cs + 1; if (cs >= NSTAGE) cs -= NSTAGE;
    }

    // ---- epilogue ----
#pragma unroll
    for (int mt = 0; mt < 4; mt++) {
        const int row0 = bm*BM + warpM*64 + mt*16 + gid;
#pragma unroll
        for (int nt = 0; nt < 4; nt++) {
            const int col = bn*BN + warpN*32 + nt*8 + tig*2;
            const float bz0 = bias[col], bz1 = bias[col+1];
#pragma unroll
            for (int half = 0; half < 2; half++) {
                const int row = row0 + half*8;
                float v0 = acc[mt][nt][half*2+0] + bz0;
                float v1 = acc[mt][nt][half*2+1] + bz1;
                if (mode == 1) {
                    *(float2*)(C + (size_t)row*N + col) = make_float2(v0, v1);
                } else {
                    const int sel = col >> 10;
                    if (sel == 0) { v0 *= QSCALE; v1 *= QSCALE; }
                    const int d2  = col & 1023;
                    const int h   = d2 >> 6;
                    const int dk  = d2 & 63;
                    const int b   = row >> 11;
                    const int s   = row & 2047;
                    __half* dst = (sel == 0) ? g_q : (sel == 1) ? g_k : g_v;
                    *(__half2*)(dst + ((size_t)(((b<<4)+h)*SEQ + s))*DK + dk)
                        = __floats2half2_rn(v0, v1);
                }
            }
        }
    }
}

// ===========================================================================
// fp16 tensor-core causal flash attention — DOUBLE-PUMPED tiles.
// Each cp.async stage holds 128 keys (K + V); the compute loop runs two
// back-to-back 64-key sub-tile passes with NO barrier between them, halving
// the wait+sync boundaries and letting sub-tile 1's softmax overlap
// sub-tile 2's QK HMMAs. Per-64-key math order identical to R15.
// ===========================================================================
#define AT_OPB (128*144)                       // 18432 B per operand per stage
#define AT_STAGEB (2*AT_OPB)                   // 36864 B
#define AT_NSTAGE 3
#define AT_SMEM_BYTES (AT_NSTAGE*AT_STAGEB)    // 110592 B

__global__ __launch_bounds__(256, 2)
void flash_attn_mma()
{
    extern __shared__ char atm[];
    const uint32_t sbase = smem_u32(atm);

    const int qt  = (int)gridDim.x - 1 - (int)blockIdx.x;   // heavy tiles first
    const int bh  = blockIdx.y;
    const int tid = threadIdx.x;
    const int w    = tid >> 5;
    const int lane = tid & 31;
    const int gid  = lane >> 2;
    const int tig  = lane & 3;

    const int r0  = w*16 + gid;
    const int qg0 = qt*128 + r0;
    const int qg1 = qg0 + 8;

    const int k_row  = (lane & 7) + ((lane >> 4) & 1)*8;   // QK (non-trans)
    const int k_colB = ((lane >> 3) & 1)*16;
    const int v_row  = (lane & 7) + ((lane >> 3) & 1)*8;   // PV (trans)
    const int v_colB = (lane >> 4)*16;

    const __half* qb = g_q + (size_t)(bh*SEQ + qt*128)*DK;
    uint32_t qa[4][4];
#pragma unroll
    for (int ks = 0; ks < 4; ks++) {
        qa[ks][0] = *(const uint32_t*)(qb + (size_t)r0*DK     + ks*16 + 2*tig);
        qa[ks][1] = *(const uint32_t*)(qb + (size_t)(r0+8)*DK + ks*16 + 2*tig);
        qa[ks][2] = *(const uint32_t*)(qb + (size_t)r0*DK     + ks*16 + 2*tig + 8);
        qa[ks][3] = *(const uint32_t*)(qb + (size_t)(r0+8)*DK + ks*16 + 2*tig + 8);
    }

    float o[8][4];
#pragma unroll
    for (int dt = 0; dt < 8; dt++)
#pragma unroll
        for (int r = 0; r < 4; r++) o[dt][r] = 0.f;
    float m0 = -1e30f, m1 = -1e30f, l0 = 0.f, l1 = 0.f;   // l: lane-partial

    const int nkt = qt + 1;                  // 128-key tiles
    const __half* kb0 = g_k + (size_t)bh*SEQ*DK;
    const __half* vb0 = g_v + (size_t)bh*SEQ*DK;

    // copy one 128-key K+V stage: 1024 16B-chunks per op, 4 per thread per op
    auto copy_kv = [&](int kt, int stage) {
        const uint32_t kbuf = sbase + (uint32_t)stage*AT_STAGEB;
        const uint32_t vbuf = kbuf + AT_OPB;
        const __half* kb = kb0 + (size_t)kt*128*DK;
        const __half* vb = vb0 + (size_t)kt*128*DK;
#pragma unroll
        for (int i = 0; i < 4; i++) {
            const int idx = tid + i*256;
            const int row = idx >> 3;            // 0..127
            const int c8  = idx & 7;
            const uint32_t soff = (uint32_t)(row*144 + c8*16);
            cp_async16(kbuf + soff, kb + row*DK + c8*8);
            cp_async16(vbuf + soff, vb + row*DK + c8*8);
        }
        cp_commit();
    };

    copy_kv(0, 0);
    if (nkt > 1) copy_kv(1, 1);

    int cs = 0;
    for (int kt = 0; kt < nkt; kt++) {
        if (kt + 1 < nkt) {
            asm volatile("cp.async.wait_group 1;");
        } else {
            asm volatile("cp.async.wait_group 0;");
        }
        __syncthreads();

        if (kt + 2 < nkt) {
            int ps = cs + 2; if (ps >= AT_NSTAGE) ps -= AT_NSTAGE;
            copy_kv(kt + 2, ps);
        }

        const uint32_t kstage = sbase + (uint32_t)cs*AT_STAGEB;
        const uint32_t vstage = kstage + AT_OPB;

        // ---- two 64-key sub-tile passes, no barrier between them ----
#pragma unroll
        for (int half = 0; half < 2; half++) {
            const uint32_t hofs = (uint32_t)half*64*144;

            // S = Q K^T (log2-domain scale folded into Q)
            float s[8][4];
#pragma unroll
            for (int nt = 0; nt < 8; nt++)
#pragma unroll
                for (int r = 0; r < 4; r++) s[nt][r] = 0.f;

            const uint32_t kAddr = kstage + hofs
                + (uint32_t)(k_row*144 + k_colB);
#pragma unroll
            for (int ks = 0; ks < 4; ks++) {
                const uint32_t ko = ks*32;
#pragma unroll
                for (int p = 0; p < 4; p++) {
                    uint32_t b00, b01, b10, b11;
                    ldsm_x4(b00, b01, b10, b11,
                            kAddr + (uint32_t)p*16*144 + ko);
                    mma_f16_16x8x16(s[2*p][0], s[2*p][1], s[2*p][2], s[2*p][3],
                                    qa[ks][0], qa[ks][1], qa[ks][2], qa[ks][3],
                                    b00, b01);
                    mma_f16_16x8x16(s[2*p+1][0], s[2*p+1][1],
                                    s[2*p+1][2], s[2*p+1][3],
                                    qa[ks][0], qa[ks][1], qa[ks][2], qa[ks][3],
                                    b10, b11);
                }
            }

            // causal mask (only the diagonal 128x128 tile can cross)
            if (kt == qt) {
#pragma unroll
                for (int nt = 0; nt < 8; nt++) {
                    const int kg = kt*128 + half*64 + nt*8 + 2*tig;
                    if (kg     > qg0) s[nt][0] = -1e30f;
                    if (kg + 1 > qg0) s[nt][1] = -1e30f;
                    if (kg     > qg1) s[nt][2] = -1e30f;
                    if (kg + 1 > qg1) s[nt][3] = -1e30f;
                }
            }

            // online softmax (log2 domain, fp32)
            float t0 = -1e30f, t1 = -1e30f;
#pragma unroll
            for (int nt = 0; nt < 8; nt++) {
                t0 = fmaxf(t0, fmaxf(s[nt][0], s[nt][1]));
                t1 = fmaxf(t1, fmaxf(s[nt][2], s[nt][3]));
            }
            t0 = fmaxf(t0, SHFL_XOR(t0, 1)); t0 = fmaxf(t0, SHFL_XOR(t0, 2));
            t1 = fmaxf(t1, SHFL_XOR(t1, 1)); t1 = fmaxf(t1, SHFL_XOR(t1, 2));
            const float m0n = fmaxf(m0, t0), m1n = fmaxf(m1, t1);
            const float c0 = ex2(m0 - m0n), c1 = ex2(m1 - m1n);
            m0 = m0n; m1 = m1n;

            float sum0 = 0.f, sum1 = 0.f;
#pragma unroll
            for (int nt = 0; nt < 8; nt++) {
                s[nt][0] = ex2(s[nt][0] - m0);
                s[nt][1] = ex2(s[nt][1] - m0);
                s[nt][2] = ex2(s[nt][2] - m1);
                s[nt][3] = ex2(s[nt][3] - m1);
                sum0 += s[nt][0] + s[nt][1];
                sum1 += s[nt][2] + s[nt][3];
            }
            l0 = l0*c0 + sum0;        // lane-partial; reduced at finalize
            l1 = l1*c1 + sum1;
#pragma unroll
            for (int dt = 0; dt < 8; dt++) {
                o[dt][0] *= c0; o[dt][1] *= c0;
                o[dt][2] *= c1; o[dt][3] *= c1;
            }

            // O += P V (P A-frags = score C-frags; V via ldmatrix.trans)
            const uint32_t vAddr = vstage + hofs
                + (uint32_t)(v_row*144 + v_colB);
#pragma unroll
            for (int kp = 0; kp < 4; kp++) {
                const uint32_t pa0 = h2pack(s[2*kp  ][0], s[2*kp  ][1]);
                const uint32_t pa1 = h2pack(s[2*kp  ][2], s[2*kp  ][3]);
                const uint32_t pa2 = h2pack(s[2*kp+1][0], s[2*kp+1][1]);
                const uint32_t pa3 = h2pack(s[2*kp+1][2], s[2*kp+1][3]);
#pragma unroll
                for (int g = 0; g < 4; g++) {
                    uint32_t v00, v01, v10, v11;
                    ldsm_x4_t(v00, v01, v10, v11,
                              vAddr + (uint32_t)kp*16*144 + g*32);
                    mma_f16_16x8x16(o[2*g][0], o[2*g][1], o[2*g][2], o[2*g][3],
                                    pa0, pa1, pa2, pa3, v00, v01);
                    mma_f16_16x8x16(o[2*g+1][0], o[2*g+1][1],
                                    o[2*g+1][2], o[2*g+1][3],
                                    pa0, pa1, pa2, pa3, v10, v11);
                }
            }
        }

        cs = cs + 1; if (cs >= AT_NSTAGE) cs -= AT_NSTAGE;
    }

    // ---- finalize: reduce l across quad, O /= l, write fp16 [B,S,D] ----
    l0 += SHFL_XOR(l0, 1); l0 += SHFL_XOR(l0, 2);
    l1 += SHFL_XOR(l1, 1); l1 += SHFL_XOR(l1, 2);
    const float inv0 = 1.f / l0, inv1 = 1.f / l1;
    const int b = bh >> 4, h = bh & 15;
    __half* ob0 = g_attn + (size_t)(b*SEQ + qg0)*DMODEL + h*DK;
    __half* ob1 = g_attn + (size_t)(b*SEQ + qg1)*DMODEL + h*DK;
#pragma unroll
    for (int dt = 0; dt < 8; dt++) {
        const int d = dt*8 + 2*tig;
        *(__half2*)(ob0 + d) = __floats2half2_rn(o[dt][0]*inv0, o[dt][1]*inv0);
        *(__half2*)(ob1 + d) = __floats2half2_rn(o[dt][2]*inv1, o[dt][3]*inv1);
    }
}

// ---------------------------------------------------------------------------
// Launch.  Inputs: x, mask, w_qkv_w, w_qkv_b, w_o_w, w_o_b
// ---------------------------------------------------------------------------
extern "C" void kernel_launch(void* const* d_in, const int* in_sizes, int n_in,
                              void* d_out, int out_size)
{
    const float* x      = (const float*)d_in[0];
    const float* wqkv   = (const float*)d_in[2];
    const float* bqkv   = (const float*)d_in[3];
    const float* wo     = (const float*)d_in[4];
    const float* bo     = (const float*)d_in[5];
    float* out = (float*)d_out;

    __half *p_attn, *p_x, *p_wqkv, *p_wo;
    cudaGetSymbolAddress((void**)&p_attn, g_attn);
    cudaGetSymbolAddress((void**)&p_x,    g_x);
    cudaGetSymbolAddress((void**)&p_wqkv, g_wqkv);
    cudaGetSymbolAddress((void**)&p_wo,   g_wo);

    cudaFuncSetAttribute(mma_gemm, cudaFuncAttributeMaxDynamicSharedMemorySize,
                         GEMM_SMEM_BYTES);
    cudaFuncSetAttribute(flash_attn_mma,
                         cudaFuncAttributeMaxDynamicSharedMemorySize,
                         AT_SMEM_BYTES);

    // 0) pre-round inputs/weights to fp16 (single launch)
    roundcopy_all<<<2048, 256>>>((const float4*)x, (const float4*)wqkv,
                                 (const float4*)wo);

    // 1) QKV projection -> g_q (xQSCALE) / g_k / g_v (fp16)
    {
        dim3 grid(3*DMODEL/BN, M_TOK/BM);   // (24, 32)
        mma_gemm<<<grid, 256, GEMM_SMEM_BYTES>>>(p_x, p_wqkv, bqkv, nullptr,
                                                 M_TOK, 3*DMODEL, DMODEL, 0);
    }
    // 2) Causal flash attention -> g_attn (fp16)
    {
        dim3 grid(SEQ/128, BATCH*NHEADS);   // (16, 32)
        flash_attn_mma<<<grid, 256, AT_SMEM_BYTES>>>();
    }
    // 3) Output projection -> d_out (fp32)
    {
        dim3 grid(DMODEL/BN, M_TOK/BM);     // (8, 32)
        mma_gemm<<<grid, 256, GEMM_SMEM_BYTES>>>(p_attn, p_wo, bo, out,
                                                 M_TOK, DMODEL, DMODEL, 1);
    }
}